// round 12
// baseline (speedup 1.0000x reference)
#include <cuda_runtime.h>
#include <cuda_bf16.h>
#include <math.h>

// Problem constants
#define BATCH 256
#define TT    200
#define DIN   128
#define HH    256
#define OUTD  118
#define G3    768   // 3*H

typedef unsigned long long ull;
typedef unsigned int uint;

// packed fp32x2 helpers
#define FMA2(acc, a, b) \
    asm("fma.rn.f32x2 %0, %1, %2, %0;" : "+l"(acc) : "l"(a), "l"(b))
#define PACK2(d, f) \
    asm("mov.b64 %0, {%1, %1};" : "=l"(d) : "f"(f))
#define UNPACK2(lo, hi, v) \
    asm("mov.b64 {%0, %1}, %2;" : "=f"(lo), "=f"(hi) : "l"(v))

__device__ __forceinline__ uint f2tf32(float f) {
    uint u;
    asm("cvt.rna.tf32.f32 %0, %1;" : "=r"(u) : "f"(f));
    return u;
}

// ---------------- scratch (static device globals; no allocation) -------------
__device__ float g_gx[(size_t)BATCH * TT * G3];      // layer-0 gx only
__device__ float g_wih1T[G3 * HH];                   // Wih1 transposed
__device__ float g_h0A[BATCH * HH];
__device__ float g_h0B[BATCH * HH];
__device__ float g_h1A[BATCH * HH];
__device__ float g_h1B[BATCH * HH];
__device__ float g_hfin[BATCH * HH];
__device__ int   g_flags[16 * 32];                   // 128B-padded per group

// ---------------------------------------------------------------------------
// tf32 tensor-core GEMM (layer-0 gx only; unchanged)
// ---------------------------------------------------------------------------
__global__ __launch_bounds__(256) void gemm_tf32_kernel(
    const float* __restrict__ A, const float* __restrict__ W,
    const float* __restrict__ bias, float* __restrict__ C,
    int M, int K)
{
    extern __shared__ uint smemU[];
    const int nb = blockIdx.x * 128;
    const int mb = blockIdx.y * 128;
    const int tid = threadIdx.x;
    const int wid = tid >> 5;
    const int lane = tid & 31;
    const int wm = wid & 1;
    const int wn = wid >> 1;
    const int r = lane >> 2;
    const int c = lane & 3;

    const float* gA = A + (size_t)mb * K;
    const float* gW = W + (size_t)nb * K;

    float acc[4][4][4];
#pragma unroll
    for (int i = 0; i < 4; i++)
#pragma unroll
        for (int j = 0; j < 4; j++)
#pragma unroll
            for (int q = 0; q < 4; q++) acc[i][j][q] = 0.f;

    const int nk = K >> 5;

    float4 pa[4], pb[4];
#pragma unroll
    for (int j = 0; j < 4; j++) {
        const int i = tid + j * 256;
        const int m = i >> 3;
        const int k4 = (i & 7) << 2;
        pa[j] = *(const float4*)(gA + (size_t)m * K + k4);
        pb[j] = *(const float4*)(gW + (size_t)m * K + k4);
    }

    for (int kc = 0; kc < nk; kc++) {
        uint* sA = smemU + (kc & 1) * 8192;
        uint* sB = sA + 4096;

#pragma unroll
        for (int j = 0; j < 4; j++) {
            const int i = tid + j * 256;
            const int m = i >> 3;
            const int k4 = (i & 7) << 2;
            const int base = m * 32 + ((((k4 >> 2) ^ (m & 7)) << 2));
            uint4 ua, ub;
            ua.x = f2tf32(pa[j].x); ua.y = f2tf32(pa[j].y);
            ua.z = f2tf32(pa[j].z); ua.w = f2tf32(pa[j].w);
            ub.x = f2tf32(pb[j].x); ub.y = f2tf32(pb[j].y);
            ub.z = f2tf32(pb[j].z); ub.w = f2tf32(pb[j].w);
            *(uint4*)(sA + base) = ua;
            *(uint4*)(sB + base) = ub;
        }
        __syncthreads();

        if (kc + 1 < nk) {
            const int kb = (kc + 1) << 5;
#pragma unroll
            for (int j = 0; j < 4; j++) {
                const int i = tid + j * 256;
                const int m = i >> 3;
                const int k4 = (i & 7) << 2;
                pa[j] = *(const float4*)(gA + (size_t)m * K + kb + k4);
                pb[j] = *(const float4*)(gW + (size_t)m * K + kb + k4);
            }
        }

#pragma unroll
        for (int kf = 0; kf < 4; kf++) {
            const int k0 = kf * 8 + c;
            const int k1 = k0 + 4;
            uint b0[4], b1[4];
#pragma unroll
            for (int nf = 0; nf < 4; nf++) {
                const int n = wn * 32 + nf * 8 + r;
                b0[nf] = sB[n * 32 + (((k0 >> 2) ^ (n & 7)) << 2) + (k0 & 3)];
                b1[nf] = sB[n * 32 + (((k1 >> 2) ^ (n & 7)) << 2) + (k1 & 3)];
            }
#pragma unroll
            for (int mf = 0; mf < 4; mf++) {
                const int m0 = wm * 64 + mf * 16 + r;
                const int m1 = m0 + 8;
                const uint a0 = sA[m0 * 32 + (((k0 >> 2) ^ (m0 & 7)) << 2) + (k0 & 3)];
                const uint a1 = sA[m1 * 32 + (((k0 >> 2) ^ (m1 & 7)) << 2) + (k0 & 3)];
                const uint a2 = sA[m0 * 32 + (((k1 >> 2) ^ (m0 & 7)) << 2) + (k1 & 3)];
                const uint a3 = sA[m1 * 32 + (((k1 >> 2) ^ (m1 & 7)) << 2) + (k1 & 3)];
#pragma unroll
                for (int nf = 0; nf < 4; nf++) {
                    asm("mma.sync.aligned.m16n8k8.row.col.f32.tf32.tf32.f32 "
                        "{%0,%1,%2,%3}, {%4,%5,%6,%7}, {%8,%9}, {%0,%1,%2,%3};"
                        : "+f"(acc[mf][nf][0]), "+f"(acc[mf][nf][1]),
                          "+f"(acc[mf][nf][2]), "+f"(acc[mf][nf][3])
                        : "r"(a0), "r"(a1), "r"(a2), "r"(a3),
                          "r"(b0[nf]), "r"(b1[nf]));
                }
            }
        }
        __syncthreads();
    }

#pragma unroll
    for (int nf = 0; nf < 4; nf++) {
        const int n = nb + wn * 32 + nf * 8 + c * 2;
        const float bb0 = bias[n], bb1 = bias[n + 1];
#pragma unroll
        for (int mf = 0; mf < 4; mf++) {
            const int m0 = mb + wm * 64 + mf * 16 + r;
            float2 v0, v1;
            v0.x = acc[mf][nf][0] + bb0; v0.y = acc[mf][nf][1] + bb1;
            v1.x = acc[mf][nf][2] + bb0; v1.y = acc[mf][nf][3] + bb1;
            *(float2*)(C + (size_t)m0 * G3 + n)       = v0;
            *(float2*)(C + (size_t)(m0 + 8) * G3 + n) = v1;
        }
    }
}

// ---------------------------------------------------------------------------
// Wih1 -> [jt][3g][256k][32j] transpose (once per call; trivial cost)
// ---------------------------------------------------------------------------
__global__ __launch_bounds__(256) void wih1_transpose_kernel(
    const float* __restrict__ Wih1, float* __restrict__ Wih1T)
{
    const int row = blockIdx.x;           // 0..767 (g*256 + j)
    const int g = row >> 8;
    const int j = row & 255;
    const int jt = j >> 5, jl = j & 31;
    const float* src = Wih1 + (size_t)row * HH;
    float* dst = Wih1T + ((size_t)(jt * 3 + g) * 256) * 32 + jl;
    for (int k = threadIdx.x; k < 256; k += 256)
        dst[(size_t)k * 32] = src[k];
}

// ---------------------------------------------------------------------------
// Fused 2-layer persistent GRU: 201 pipelined iterations instead of 400+GEMM.
// Iteration i: L0 step i (h0[i] from h0[i-1]) and L1 step i-1
// (h1[i-1] from gx1=Wih1T@h0[i-1]+bih1 and h1[i-2]).
// grid (8 jt, 16 mt), 128 threads, 224KB smem -> 1 CTA/SM.
// ---------------------------------------------------------------------------
#define FUSED_SMEM_BYTES (57344 * 4)   // 224KB

__device__ __forceinline__ float sigm(float x) {
    return __fdividef(1.f, 1.f + __expf(-x));
}
__device__ __forceinline__ float tanh_fast(float x) {
    return 1.f - 2.f * __fdividef(1.f, __expf(2.f * x) + 1.f);
}

__global__ __launch_bounds__(128) void gru_fused_kernel(
    const float* __restrict__ Whh0, const float* __restrict__ bhh0,
    const float* __restrict__ Whh1, const float* __restrict__ bhh1,
    const float* __restrict__ bih1, const float* __restrict__ Wih1T,
    const float* __restrict__ gx0,
    float* __restrict__ h0A, float* __restrict__ h0B,
    float* __restrict__ h1A, float* __restrict__ h1B,
    float* __restrict__ hfin, int* __restrict__ flags)
{
    extern __shared__ float smem[];
    float* sW0 = smem;               // [3g][256k][32j]
    float* sW1 = smem + 24576;
    float* s0  = smem + 49152;       // h0 stage [256k][16m]
    float* s1  = smem + 53248;       // h1 stage [256k][16m]

    const int jt = blockIdx.x;
    const int mt = blockIdx.y;
    const int jb = jt * 32;
    const int mb = mt * 16;
    const int tid = threadIdx.x;
    const int wid = tid >> 5;
    const int lane = tid & 31;

    // FMA/gate mapping
    const int mh = lane >> 4;
    const int jp = lane & 15;
    const int mo = wid * 4 + 2 * mh;       // m0 (m1 = mo+1)
    const int jo = jb + 2 * jp;            // j0 (j1 = jo+1)

    // stage mapping: warp handles k block [wid*64, +64)
    const int m_l = lane & 15;
    const int kh  = wid * 64 + (lane >> 4) * 32;

    // ---- init ----
    for (int i = tid; i < 4096; i += 128) { s0[i] = 0.f; s1[i] = 0.f; }
    if (tid < 96) {
        const int g = tid >> 5, j = tid & 31;
        const float* r0 = Whh0 + (size_t)(g * HH + jb + j) * HH;
        const float* r1 = Whh1 + (size_t)(g * HH + jb + j) * HH;
        float* d0 = sW0 + g * 8192 + j;
        float* d1 = sW1 + g * 8192 + j;
#pragma unroll 4
        for (int k = 0; k < 256; k += 4) {
            float4 v = *(const float4*)(r0 + k);
            d0[(k + 0) * 32] = v.x; d0[(k + 1) * 32] = v.y;
            d0[(k + 2) * 32] = v.z; d0[(k + 3) * 32] = v.w;
            float4 u = *(const float4*)(r1 + k);
            d1[(k + 0) * 32] = u.x; d1[(k + 1) * 32] = u.y;
            d1[(k + 2) * 32] = u.z; d1[(k + 3) * 32] = u.w;
        }
    }

    const float2 b0r = *(const float2*)(bhh0 + jo);
    const float2 b0z = *(const float2*)(bhh0 + HH + jo);
    const float2 b0n = *(const float2*)(bhh0 + 2 * HH + jo);
    const float2 b1r = *(const float2*)(bhh1 + jo);
    const float2 b1z = *(const float2*)(bhh1 + HH + jo);
    const float2 b1n = *(const float2*)(bhh1 + 2 * HH + jo);
    const float2 i1r = *(const float2*)(bih1 + jo);
    const float2 i1z = *(const float2*)(bih1 + HH + jo);
    const float2 i1n = *(const float2*)(bih1 + 2 * HH + jo);

    const int bb0 = mb + mo, bb1 = bb0 + 1;
    const float* gxp0 = gx0 + (size_t)bb0 * TT * G3;
    const float* gxp1 = gx0 + (size_t)bb1 * TT * G3;
    int* const flagp = flags + mt * 32;
    const float* wiR = Wih1T + ((size_t)(jt * 3 + 0) * 256) * 32 + 2 * jp;
    const float* wiZ = Wih1T + ((size_t)(jt * 3 + 1) * 256) * 32 + 2 * jp;
    const float* wiN = Wih1T + ((size_t)(jt * 3 + 2) * 256) * 32 + 2 * jp;

    __syncthreads();

    for (int i = 0; i <= TT; i++) {
        // ---- prefetch gx0[i] (lands during the wait) ----
        float2 gr0 = {0.f, 0.f}, gz0 = {0.f, 0.f}, gn0 = {0.f, 0.f};
        float2 gr1 = {0.f, 0.f}, gz1 = {0.f, 0.f}, gn1 = {0.f, 0.f};
        if (i < TT) {
            const float* p0 = gxp0 + (size_t)i * G3;
            const float* p1 = gxp1 + (size_t)i * G3;
            gr0 = __ldg((const float2*)(p0 + jo));
            gz0 = __ldg((const float2*)(p0 + HH + jo));
            gn0 = __ldg((const float2*)(p0 + 2 * HH + jo));
            gr1 = __ldg((const float2*)(p1 + jo));
            gz1 = __ldg((const float2*)(p1 + HH + jo));
            gn1 = __ldg((const float2*)(p1 + 2 * HH + jo));
        }

        // ---- wait + stage h0[i-1], h1[i-2] ----
        if (i > 0) {
            if (lane == 0) {
                const int tgt = 8 * i;
                int v;
                do {
                    asm volatile("ld.global.acquire.gpu.b32 %0, [%1];"
                                 : "=r"(v) : "l"(flagp));
                } while (v < tgt);
            }
            __syncwarp();
            const int p = (i - 1) & 1;
            const float* src0 = (p ? h0B : h0A) + (size_t)(mb + m_l) * HH + kh;
            const float* src1 = (p ? h1B : h1A) + (size_t)(mb + m_l) * HH + kh;
#pragma unroll
            for (int q = 0; q < 32; q += 4) {
                float4 v = __ldcg((const float4*)(src0 + q));
                s0[(kh + q + 0) * 16 + m_l] = v.x;
                s0[(kh + q + 1) * 16 + m_l] = v.y;
                s0[(kh + q + 2) * 16 + m_l] = v.z;
                s0[(kh + q + 3) * 16 + m_l] = v.w;
                float4 u = __ldcg((const float4*)(src1 + q));
                s1[(kh + q + 0) * 16 + m_l] = u.x;
                s1[(kh + q + 1) * 16 + m_l] = u.y;
                s1[(kh + q + 2) * 16 + m_l] = u.z;
                s1[(kh + q + 3) * 16 + m_l] = u.w;
            }
        }
        __syncthreads();

        // ---- fused triple GEMM ----
        ull aA0r = 0, aA0z = 0, aA0n = 0, aA1r = 0, aA1z = 0, aA1n = 0;  // Whh0@h0
        ull aB0r = 0, aB0z = 0, aB0n = 0, aB1r = 0, aB1z = 0, aB1n = 0;  // Wih1@h0
        ull aC0r = 0, aC0z = 0, aC0n = 0, aC1r = 0, aC1z = 0, aC1n = 0;  // Whh1@h1
        {
            const float* h0P = s0 + mo;
            const float* h1P = s1 + mo;
            const float* w0r = sW0 + 2 * jp;
            const float* w0z = w0r + 8192;
            const float* w0n = w0z + 8192;
            const float* w1r = sW1 + 2 * jp;
            const float* w1z = w1r + 8192;
            const float* w1n = w1z + 8192;
#pragma unroll 8
            for (int k = 0; k < 256; k++) {
                const float2 h0v = *(const float2*)(h0P + k * 16);
                const float2 h1v = *(const float2*)(h1P + k * 16);
                ull p00, p01, p10, p11;
                PACK2(p00, h0v.x); PACK2(p01, h0v.y);
                PACK2(p10, h1v.x); PACK2(p11, h1v.y);
                ull w;
                w = *(const ull*)(w0r + k * 32); FMA2(aA0r, p00, w); FMA2(aA1r, p01, w);
                w = *(const ull*)(w0z + k * 32); FMA2(aA0z, p00, w); FMA2(aA1z, p01, w);
                w = *(const ull*)(w0n + k * 32); FMA2(aA0n, p00, w); FMA2(aA1n, p01, w);
                w = *(const ull*)(wiR + (size_t)k * 32); FMA2(aB0r, p00, w); FMA2(aB1r, p01, w);
                w = *(const ull*)(wiZ + (size_t)k * 32); FMA2(aB0z, p00, w); FMA2(aB1z, p01, w);
                w = *(const ull*)(wiN + (size_t)k * 32); FMA2(aB0n, p00, w); FMA2(aB1n, p01, w);
                w = *(const ull*)(w1r + k * 32); FMA2(aC0r, p10, w); FMA2(aC1r, p11, w);
                w = *(const ull*)(w1z + k * 32); FMA2(aC0z, p10, w); FMA2(aC1z, p11, w);
                w = *(const ull*)(w1n + k * 32); FMA2(aC0n, p10, w); FMA2(aC1n, p11, w);
            }
        }

        const int pw = i & 1;
        float* wb0 = pw ? h0B : h0A;
        float* wb1 = pw ? h1B : h1A;

        // ---- L0 gates -> h0[i] ----
        if (i < TT) {
            float ar0, ar1, az0, az1, an0, an1;   // m0 row, j0/j1
            float br0_, br1_, bz0_, bz1_, bn0_, bn1_;  // m1 row
            UNPACK2(ar0, ar1, aA0r); UNPACK2(az0, az1, aA0z); UNPACK2(an0, an1, aA0n);
            UNPACK2(br0_, br1_, aA1r); UNPACK2(bz0_, bz1_, aA1z); UNPACK2(bn0_, bn1_, aA1n);

            const float2 ho_j0 = *(const float2*)(s0 + (size_t)jo * 16 + mo);
            const float2 ho_j1 = *(const float2*)(s0 + (size_t)(jo + 1) * 16 + mo);

            const float R00 = sigm(gr0.x + ar0 + b0r.x);
            const float R01 = sigm(gr0.y + ar1 + b0r.y);
            const float R10 = sigm(gr1.x + br0_ + b0r.x);
            const float R11 = sigm(gr1.y + br1_ + b0r.y);
            const float Z00 = sigm(gz0.x + az0 + b0z.x);
            const float Z01 = sigm(gz0.y + az1 + b0z.y);
            const float Z10 = sigm(gz1.x + bz0_ + b0z.x);
            const float Z11 = sigm(gz1.y + bz1_ + b0z.y);
            const float N00 = tanh_fast(gn0.x + R00 * (an0 + b0n.x));
            const float N01 = tanh_fast(gn0.y + R01 * (an1 + b0n.y));
            const float N10 = tanh_fast(gn1.x + R10 * (bn0_ + b0n.x));
            const float N11 = tanh_fast(gn1.y + R11 * (bn1_ + b0n.y));

            const float h00 = (1.f - Z00) * N00 + Z00 * ho_j0.x;
            const float h01 = (1.f - Z01) * N01 + Z01 * ho_j1.x;
            const float h10 = (1.f - Z10) * N10 + Z10 * ho_j0.y;
            const float h11 = (1.f - Z11) * N11 + Z11 * ho_j1.y;

            float* d0 = wb0 + (size_t)bb0 * HH + jo;
            float* d1 = wb0 + (size_t)bb1 * HH + jo;
            asm volatile("st.global.cg.v2.f32 [%0], {%1,%2};"
                         :: "l"(d0), "f"(h00), "f"(h01));
            asm volatile("st.global.cg.v2.f32 [%0], {%1,%2};"
                         :: "l"(d1), "f"(h10), "f"(h11));
        }

        // ---- L1 gates -> h1[i-1] (zeros at i==0) ----
        {
            float h00 = 0.f, h01 = 0.f, h10 = 0.f, h11 = 0.f;
            if (i > 0) {
                float xr0, xr1, xz0, xz1, xn0, xn1;
                float yr0, yr1, yz0, yz1, yn0, yn1;
                UNPACK2(xr0, xr1, aB0r); UNPACK2(xz0, xz1, aB0z); UNPACK2(xn0, xn1, aB0n);
                UNPACK2(yr0, yr1, aB1r); UNPACK2(yz0, yz1, aB1z); UNPACK2(yn0, yn1, aB1n);
                float cr0, cr1, cz0, cz1, cn0, cn1;
                float dr0, dr1, dz0, dz1, dn0, dn1;
                UNPACK2(cr0, cr1, aC0r); UNPACK2(cz0, cz1, aC0z); UNPACK2(cn0, cn1, aC0n);
                UNPACK2(dr0, dr1, aC1r); UNPACK2(dz0, dz1, aC1z); UNPACK2(dn0, dn1, aC1n);

                const float2 h1o_j0 = *(const float2*)(s1 + (size_t)jo * 16 + mo);
                const float2 h1o_j1 = *(const float2*)(s1 + (size_t)(jo + 1) * 16 + mo);

                const float R00 = sigm((xr0 + i1r.x) + (cr0 + b1r.x));
                const float R01 = sigm((xr1 + i1r.y) + (cr1 + b1r.y));
                const float R10 = sigm((yr0 + i1r.x) + (dr0 + b1r.x));
                const float R11 = sigm((yr1 + i1r.y) + (dr1 + b1r.y));
                const float Z00 = sigm((xz0 + i1z.x) + (cz0 + b1z.x));
                const float Z01 = sigm((xz1 + i1z.y) + (cz1 + b1z.y));
                const float Z10 = sigm((yz0 + i1z.x) + (dz0 + b1z.x));
                const float Z11 = sigm((yz1 + i1z.y) + (dz1 + b1z.y));
                const float N00 = tanh_fast((xn0 + i1n.x) + R00 * (cn0 + b1n.x));
                const float N01 = tanh_fast((xn1 + i1n.y) + R01 * (cn1 + b1n.y));
                const float N10 = tanh_fast((yn0 + i1n.x) + R10 * (dn0 + b1n.x));
                const float N11 = tanh_fast((yn1 + i1n.y) + R11 * (dn1 + b1n.y));

                h00 = (1.f - Z00) * N00 + Z00 * h1o_j0.x;
                h01 = (1.f - Z01) * N01 + Z01 * h1o_j1.x;
                h10 = (1.f - Z10) * N10 + Z10 * h1o_j0.y;
                h11 = (1.f - Z11) * N11 + Z11 * h1o_j1.y;
            }
            float* d0 = wb1 + (size_t)bb0 * HH + jo;
            float* d1 = wb1 + (size_t)bb1 * HH + jo;
            asm volatile("st.global.cg.v2.f32 [%0], {%1,%2};"
                         :: "l"(d0), "f"(h00), "f"(h01));
            asm volatile("st.global.cg.v2.f32 [%0], {%1,%2};"
                         :: "l"(d1), "f"(h10), "f"(h11));
            if (i == TT) {
                float2 v0; v0.x = h00; v0.y = h01;
                float2 v1; v1.x = h10; v1.y = h11;
                *(float2*)(hfin + (size_t)bb0 * HH + jo) = v0;
                *(float2*)(hfin + (size_t)bb1 * HH + jo) = v1;
            }
        }

        __syncthreads();   // all publishes of this iteration issued
        if (tid == 0) {
            asm volatile("red.release.gpu.global.add.u32 [%0], %1;"
                         :: "l"(flagp), "r"(1) : "memory");
        }
    }
}

// ---------------------------------------------------------------------------
// Final FC
// ---------------------------------------------------------------------------
__global__ __launch_bounds__(128) void fc_kernel(
    const float* __restrict__ hfin, const float* __restrict__ W,
    const float* __restrict__ bias, float* __restrict__ out)
{
    __shared__ float hs[HH];
    const int b = blockIdx.x;
    const float* hrow = hfin + (size_t)b * HH;
    for (int i = threadIdx.x; i < HH; i += 128) hs[i] = hrow[i];
    __syncthreads();
    const int o = threadIdx.x;
    if (o < OUTD) {
        float acc = bias[o];
        const float* wr = W + (size_t)o * HH;
#pragma unroll 8
        for (int k = 0; k < HH; k++) acc += hs[k] * wr[k];
        out[(size_t)b * OUTD + o] = acc;
    }
}

// ---------------------------------------------------------------------------
extern "C" void kernel_launch(void* const* d_in, const int* in_sizes, int n_in,
                              void* d_out, int out_size)
{
    const float* x    = (const float*)d_in[0];
    const float* Wih0 = (const float*)d_in[1];
    const float* Whh0 = (const float*)d_in[2];
    const float* bih0 = (const float*)d_in[3];
    const float* bhh0 = (const float*)d_in[4];
    const float* Wih1 = (const float*)d_in[5];
    const float* Whh1 = (const float*)d_in[6];
    const float* bih1 = (const float*)d_in[7];
    const float* bhh1 = (const float*)d_in[8];
    const float* fcW  = (const float*)d_in[9];
    const float* fcb  = (const float*)d_in[10];
    float* out = (float*)d_out;

    float *gx, *wih1T, *h0A, *h0B, *h1A, *h1B, *hfin;
    int* flags;
    cudaGetSymbolAddress((void**)&gx, g_gx);
    cudaGetSymbolAddress((void**)&wih1T, g_wih1T);
    cudaGetSymbolAddress((void**)&h0A, g_h0A);
    cudaGetSymbolAddress((void**)&h0B, g_h0B);
    cudaGetSymbolAddress((void**)&h1A, g_h1A);
    cudaGetSymbolAddress((void**)&h1B, g_h1B);
    cudaGetSymbolAddress((void**)&hfin, g_hfin);
    cudaGetSymbolAddress((void**)&flags, g_flags);

    static bool attr_set = false;
    if (!attr_set) {
        cudaFuncSetAttribute(gru_fused_kernel,
                             cudaFuncAttributeMaxDynamicSharedMemorySize,
                             FUSED_SMEM_BYTES);
        cudaFuncSetAttribute(gemm_tf32_kernel,
                             cudaFuncAttributeMaxDynamicSharedMemorySize,
                             64 * 1024);
        attr_set = true;
    }

    const dim3 gemmGrid(G3 / 128, (BATCH * TT) / 128);
    const dim3 fusedGrid(8, 16);
    const int gemmSmem = 64 * 1024;

    // layer-0 gx (tf32 tensor cores) + Wih1 transpose + flag reset
    gemm_tf32_kernel<<<gemmGrid, 256, gemmSmem>>>(x, Wih0, bih0, gx, BATCH * TT, DIN);
    wih1_transpose_kernel<<<G3, 256>>>(Wih1, wih1T);
    cudaMemsetAsync(flags, 0, 16 * 32 * sizeof(int));

    // fused 2-layer recurrence (201 pipelined steps)
    gru_fused_kernel<<<fusedGrid, 128, FUSED_SMEM_BYTES>>>(
        Whh0, bhh0, Whh1, bhh1, bih1, wih1T, gx,
        h0A, h0B, h1A, h1B, hfin, flags);

    // final FC
    fc_kernel<<<BATCH, 128>>>(hfin, fcW, fcb, out);
}

// round 13
// speedup vs baseline: 8.3175x; 8.3175x over previous
#include <cuda_runtime.h>
#include <cuda_bf16.h>
#include <math.h>

// Problem constants
#define BATCH 256
#define TT    200
#define DIN   128
#define HH    256
#define OUTD  118
#define G3    768   // 3*H

typedef unsigned long long ull;
typedef unsigned int uint;

// packed fp32x2 helpers
#define FMA2(acc, a, b) \
    asm("fma.rn.f32x2 %0, %1, %2, %0;" : "+l"(acc) : "l"(a), "l"(b))
#define PACK2(d, f) \
    asm("mov.b64 %0, {%1, %1};" : "=l"(d) : "f"(f))
#define UNPACK2(lo, hi, v) \
    asm("mov.b64 {%0, %1}, %2;" : "=f"(lo), "=f"(hi) : "l"(v))

__device__ __forceinline__ uint f2tf32(float f) {
    uint u;
    asm("cvt.rna.tf32.f32 %0, %1;" : "=r"(u) : "f"(f));
    return u;
}

// ---------------- scratch (static device globals; no allocation) -------------
__device__ float g_gx[(size_t)BATCH * TT * G3];
__device__ float g_hseq[(size_t)BATCH * TT * HH];
__device__ float g_hA[BATCH * HH];
__device__ float g_hB[BATCH * HH];
__device__ float g_hfin[BATCH * HH];
__device__ int   g_flags[16 * 32];   // one flag per group, 128B padded

// ---------------------------------------------------------------------------
// tf32 tensor-core GEMM (unchanged from R4)
// ---------------------------------------------------------------------------
__global__ __launch_bounds__(256) void gemm_tf32_kernel(
    const float* __restrict__ A, const float* __restrict__ W,
    const float* __restrict__ bias, float* __restrict__ C,
    int M, int K)
{
    extern __shared__ uint smemU[];
    const int nb = blockIdx.x * 128;
    const int mb = blockIdx.y * 128;
    const int tid = threadIdx.x;
    const int wid = tid >> 5;
    const int lane = tid & 31;
    const int wm = wid & 1;
    const int wn = wid >> 1;
    const int r = lane >> 2;
    const int c = lane & 3;

    const float* gA = A + (size_t)mb * K;
    const float* gW = W + (size_t)nb * K;

    float acc[4][4][4];
#pragma unroll
    for (int i = 0; i < 4; i++)
#pragma unroll
        for (int j = 0; j < 4; j++)
#pragma unroll
            for (int q = 0; q < 4; q++) acc[i][j][q] = 0.f;

    const int nk = K >> 5;

    float4 pa[4], pb[4];
#pragma unroll
    for (int j = 0; j < 4; j++) {
        const int i = tid + j * 256;
        const int m = i >> 3;
        const int k4 = (i & 7) << 2;
        pa[j] = *(const float4*)(gA + (size_t)m * K + k4);
        pb[j] = *(const float4*)(gW + (size_t)m * K + k4);
    }

    for (int kc = 0; kc < nk; kc++) {
        uint* sA = smemU + (kc & 1) * 8192;
        uint* sB = sA + 4096;

#pragma unroll
        for (int j = 0; j < 4; j++) {
            const int i = tid + j * 256;
            const int m = i >> 3;
            const int k4 = (i & 7) << 2;
            const int base = m * 32 + ((((k4 >> 2) ^ (m & 7)) << 2));
            uint4 ua, ub;
            ua.x = f2tf32(pa[j].x); ua.y = f2tf32(pa[j].y);
            ua.z = f2tf32(pa[j].z); ua.w = f2tf32(pa[j].w);
            ub.x = f2tf32(pb[j].x); ub.y = f2tf32(pb[j].y);
            ub.z = f2tf32(pb[j].z); ub.w = f2tf32(pb[j].w);
            *(uint4*)(sA + base) = ua;
            *(uint4*)(sB + base) = ub;
        }
        __syncthreads();

        if (kc + 1 < nk) {
            const int kb = (kc + 1) << 5;
#pragma unroll
            for (int j = 0; j < 4; j++) {
                const int i = tid + j * 256;
                const int m = i >> 3;
                const int k4 = (i & 7) << 2;
                pa[j] = *(const float4*)(gA + (size_t)m * K + kb + k4);
                pb[j] = *(const float4*)(gW + (size_t)m * K + kb + k4);
            }
        }

#pragma unroll
        for (int kf = 0; kf < 4; kf++) {
            const int k0 = kf * 8 + c;
            const int k1 = k0 + 4;
            uint b0[4], b1[4];
#pragma unroll
            for (int nf = 0; nf < 4; nf++) {
                const int n = wn * 32 + nf * 8 + r;
                b0[nf] = sB[n * 32 + (((k0 >> 2) ^ (n & 7)) << 2) + (k0 & 3)];
                b1[nf] = sB[n * 32 + (((k1 >> 2) ^ (n & 7)) << 2) + (k1 & 3)];
            }
#pragma unroll
            for (int mf = 0; mf < 4; mf++) {
                const int m0 = wm * 64 + mf * 16 + r;
                const int m1 = m0 + 8;
                const uint a0 = sA[m0 * 32 + (((k0 >> 2) ^ (m0 & 7)) << 2) + (k0 & 3)];
                const uint a1 = sA[m1 * 32 + (((k0 >> 2) ^ (m1 & 7)) << 2) + (k0 & 3)];
                const uint a2 = sA[m0 * 32 + (((k1 >> 2) ^ (m0 & 7)) << 2) + (k1 & 3)];
                const uint a3 = sA[m1 * 32 + (((k1 >> 2) ^ (m1 & 7)) << 2) + (k1 & 3)];
#pragma unroll
                for (int nf = 0; nf < 4; nf++) {
                    asm("mma.sync.aligned.m16n8k8.row.col.f32.tf32.tf32.f32 "
                        "{%0,%1,%2,%3}, {%4,%5,%6,%7}, {%8,%9}, {%0,%1,%2,%3};"
                        : "+f"(acc[mf][nf][0]), "+f"(acc[mf][nf][1]),
                          "+f"(acc[mf][nf][2]), "+f"(acc[mf][nf][3])
                        : "r"(a0), "r"(a1), "r"(a2), "r"(a3),
                          "r"(b0[nf]), "r"(b1[nf]));
                }
            }
        }
        __syncthreads();
    }

#pragma unroll
    for (int nf = 0; nf < 4; nf++) {
        const int n = nb + wn * 32 + nf * 8 + c * 2;
        const float bb0 = bias[n], bb1 = bias[n + 1];
#pragma unroll
        for (int mf = 0; mf < 4; mf++) {
            const int m0 = mb + wm * 64 + mf * 16 + r;
            float2 v0, v1;
            v0.x = acc[mf][nf][0] + bb0; v0.y = acc[mf][nf][1] + bb1;
            v1.x = acc[mf][nf][2] + bb0; v1.y = acc[mf][nf][3] + bb1;
            *(float2*)(C + (size_t)m0 * G3 + n)       = v0;
            *(float2*)(C + (size_t)(m0 + 8) * G3 + n) = v1;
        }
    }
}

// ---------------------------------------------------------------------------
// Persistent GRU layer kernel — EXACT R5 structure (4-warp split-K,
// 128 threads, bulk group flag) with only non-structural fixes:
// padded flags, gx prefetch before wait, red.release instead of
// threadfence+atomic, optional hseq writes moved after the release.
// ---------------------------------------------------------------------------
#define SW_FLOATS (3 * 256 * 32)
#define SH_FLOATS (256 * 16)
#define SP_FLOATS (4 * 3 * 16 * 32)
#define LAYER_SMEM_FLOATS (SW_FLOATS + SH_FLOATS + SP_FLOATS)

__device__ __forceinline__ float sigm(float x) {
    return __fdividef(1.f, 1.f + __expf(-x));
}
__device__ __forceinline__ float tanh_fast(float x) {
    return 1.f - 2.f * __fdividef(1.f, __expf(2.f * x) + 1.f);
}

__global__ __launch_bounds__(128) void gru_layer_kernel(
    float* __restrict__ hA, float* __restrict__ hB,
    const float* __restrict__ Whh, const float* __restrict__ bhh,
    const float* __restrict__ gx,
    float* __restrict__ hseq,
    float* __restrict__ hfin,
    int* __restrict__ flags,
    int write_seq)
{
    extern __shared__ float smem[];
    float* sW = smem;                       // [(g*256+k)*32 + j]
    float* sh = smem + SW_FLOATS;           // [k*16 + m]
    float* sp = sh + SH_FLOATS;             // [((w*3+g)*16+m)*32 + j]

    const int jt = blockIdx.x;
    const int mt = blockIdx.y;
    const int jb = jt * 32;
    const int mb = mt * 16;
    const int tid = threadIdx.x;
    const int wid = tid >> 5;
    const int lane = tid & 31;

    // FMA-loop lane mapping (R5)
    const int mq = (lane >> 3) * 4;         // m-quad base
    const int j0 = (lane & 7) * 4;          // j-quad base
    const int k0 = wid * 64;                // K slice

    // reduction mapping (R5): 4 consecutive j per thread
    const int m_r = tid >> 3;               // 0..15
    const int j_r = (tid & 7) * 4;          // 0..28

    // ---- one-time: load Whh tile into smem [g][k][j] ----
    if (tid < 96) {
        const int g = tid >> 5;
        const int j = tid & 31;
        const float* wrow = Whh + (size_t)(g * HH + jb + j) * HH;
        float* dst = sW + (size_t)g * 256 * 32 + j;
#pragma unroll 4
        for (int k = 0; k < 256; k += 4) {
            float4 v = *(const float4*)(wrow + k);
            dst[(k + 0) * 32] = v.x;
            dst[(k + 1) * 32] = v.y;
            dst[(k + 2) * 32] = v.z;
            dst[(k + 3) * 32] = v.w;
        }
    }

    const float4 br4 = *(const float4*)(bhh + jb + j_r);
    const float4 bz4 = *(const float4*)(bhh + HH + jb + j_r);
    const float4 bn4 = *(const float4*)(bhh + 2 * HH + jb + j_r);

    // h-stage loader mapping (R5)
    const int sm_ = tid & 15;
    const int skb = (tid >> 4) * 32;

    const int b_r = mb + m_r;
    const float* gxb = gx + (size_t)b_r * TT * G3;
    int* const flagp = flags + mt * 32;     // padded: one 128B line per group

    __syncthreads();

    for (int t = 0; t < TT; t++) {
        const float* rb = (t & 1) ? hB : hA;
        float*       wb = (t & 1) ? hA : hB;

        // ---- gx prefetch BEFORE the wait (lands during the spin) ----
        const float* gxp = gxb + (size_t)t * G3;
        const float4 gr4 = __ldg((const float4*)(gxp + jb + j_r));
        const float4 gz4 = __ldg((const float4*)(gxp + HH + jb + j_r));
        const float4 gn4 = __ldg((const float4*)(gxp + 2 * HH + jb + j_r));

        if (t > 0) {
            if (tid == 0) {
                const int tgt = 8 * t;
                int v;
                do {
                    asm volatile("ld.global.acquire.gpu.b32 %0, [%1];"
                                 : "=r"(v) : "l"(flagp));
                } while (v < tgt);
            }
            __syncthreads();
        }

        // stage h tile [k=256][m=16] (R5 mapping)
        {
            const float* src = rb + (size_t)(mb + sm_) * HH + skb;
#pragma unroll
            for (int i = 0; i < 32; i += 4) {
                float4 v;
                v.x = __ldcg(src + i);
                v.y = __ldcg(src + i + 1);
                v.z = __ldcg(src + i + 2);
                v.w = __ldcg(src + i + 3);
                sh[(skb + i + 0) * 16 + sm_] = v.x;
                sh[(skb + i + 1) * 16 + sm_] = v.y;
                sh[(skb + i + 2) * 16 + sm_] = v.z;
                sh[(skb + i + 3) * 16 + sm_] = v.w;
            }
        }
        __syncthreads();

        // ---- warp-split-K FMA loop (R5) ----
        ull acc[4][3][2];
#pragma unroll
        for (int m = 0; m < 4; m++)
#pragma unroll
            for (int g = 0; g < 3; g++) {
                acc[m][g][0] = 0ull;
                acc[m][g][1] = 0ull;
            }
        {
            const float* hP  = sh + k0 * 16 + mq;
            const float* w0P = sW + (size_t)(0 * 256 + k0) * 32 + j0;
            const float* w1P = sW + (size_t)(1 * 256 + k0) * 32 + j0;
            const float* w2P = sW + (size_t)(2 * 256 + k0) * 32 + j0;
#pragma unroll 4
            for (int kk = 0; kk < 64; kk++) {
                const float4 hq = *(const float4*)(hP + kk * 16);
                ull h0, h1, h2, h3;
                PACK2(h0, hq.x); PACK2(h1, hq.y);
                PACK2(h2, hq.z); PACK2(h3, hq.w);

                const ull* wr = (const ull*)(w0P + (size_t)kk * 32);
                const ull wr0 = wr[0], wr1 = wr[1];
                FMA2(acc[0][0][0], h0, wr0); FMA2(acc[0][0][1], h0, wr1);
                FMA2(acc[1][0][0], h1, wr0); FMA2(acc[1][0][1], h1, wr1);
                FMA2(acc[2][0][0], h2, wr0); FMA2(acc[2][0][1], h2, wr1);
                FMA2(acc[3][0][0], h3, wr0); FMA2(acc[3][0][1], h3, wr1);

                const ull* wz = (const ull*)(w1P + (size_t)kk * 32);
                const ull wz0 = wz[0], wz1 = wz[1];
                FMA2(acc[0][1][0], h0, wz0); FMA2(acc[0][1][1], h0, wz1);
                FMA2(acc[1][1][0], h1, wz0); FMA2(acc[1][1][1], h1, wz1);
                FMA2(acc[2][1][0], h2, wz0); FMA2(acc[2][1][1], h2, wz1);
                FMA2(acc[3][1][0], h3, wz0); FMA2(acc[3][1][1], h3, wz1);

                const ull* wn = (const ull*)(w2P + (size_t)kk * 32);
                const ull wn0 = wn[0], wn1 = wn[1];
                FMA2(acc[0][2][0], h0, wn0); FMA2(acc[0][2][1], h0, wn1);
                FMA2(acc[1][2][0], h1, wn0); FMA2(acc[1][2][1], h1, wn1);
                FMA2(acc[2][2][0], h2, wn0); FMA2(acc[2][2][1], h2, wn1);
                FMA2(acc[3][2][0], h3, wn0); FMA2(acc[3][2][1], h3, wn1);
            }
        }

        // store partials (R5)
#pragma unroll
        for (int m = 0; m < 4; m++) {
#pragma unroll
            for (int g = 0; g < 3; g++) {
                ull* dst = (ull*)(sp + (size_t)(((wid * 3 + g) * 16) + mq + m) * 32 + j0);
                dst[0] = acc[m][g][0];
                dst[1] = acc[m][g][1];
            }
        }
        __syncthreads();

        // ---- reduce across 4 warps + gates (R5) ----
        float ghr[4], ghz[4], ghn[4];
        {
            float4 s0, s1, s2, s3;
            s0 = *(const float4*)(sp + (size_t)((0 * 3 + 0) * 16 + m_r) * 32 + j_r);
            s1 = *(const float4*)(sp + (size_t)((1 * 3 + 0) * 16 + m_r) * 32 + j_r);
            s2 = *(const float4*)(sp + (size_t)((2 * 3 + 0) * 16 + m_r) * 32 + j_r);
            s3 = *(const float4*)(sp + (size_t)((3 * 3 + 0) * 16 + m_r) * 32 + j_r);
            ghr[0] = (s0.x + s1.x) + (s2.x + s3.x);
            ghr[1] = (s0.y + s1.y) + (s2.y + s3.y);
            ghr[2] = (s0.z + s1.z) + (s2.z + s3.z);
            ghr[3] = (s0.w + s1.w) + (s2.w + s3.w);
            s0 = *(const float4*)(sp + (size_t)((0 * 3 + 1) * 16 + m_r) * 32 + j_r);
            s1 = *(const float4*)(sp + (size_t)((1 * 3 + 1) * 16 + m_r) * 32 + j_r);
            s2 = *(const float4*)(sp + (size_t)((2 * 3 + 1) * 16 + m_r) * 32 + j_r);
            s3 = *(const float4*)(sp + (size_t)((3 * 3 + 1) * 16 + m_r) * 32 + j_r);
            ghz[0] = (s0.x + s1.x) + (s2.x + s3.x);
            ghz[1] = (s0.y + s1.y) + (s2.y + s3.y);
            ghz[2] = (s0.z + s1.z) + (s2.z + s3.z);
            ghz[3] = (s0.w + s1.w) + (s2.w + s3.w);
            s0 = *(const float4*)(sp + (size_t)((0 * 3 + 2) * 16 + m_r) * 32 + j_r);
            s1 = *(const float4*)(sp + (size_t)((1 * 3 + 2) * 16 + m_r) * 32 + j_r);
            s2 = *(const float4*)(sp + (size_t)((2 * 3 + 2) * 16 + m_r) * 32 + j_r);
            s3 = *(const float4*)(sp + (size_t)((3 * 3 + 2) * 16 + m_r) * 32 + j_r);
            ghn[0] = (s0.x + s1.x) + (s2.x + s3.x);
            ghn[1] = (s0.y + s1.y) + (s2.y + s3.y);
            ghn[2] = (s0.z + s1.z) + (s2.z + s3.z);
            ghn[3] = (s0.w + s1.w) + (s2.w + s3.w);
        }

        const float grr[4] = {gr4.x, gr4.y, gr4.z, gr4.w};
        const float gzz[4] = {gz4.x, gz4.y, gz4.z, gz4.w};
        const float gnn[4] = {gn4.x, gn4.y, gn4.z, gn4.w};
        const float brr[4] = {br4.x, br4.y, br4.z, br4.w};
        const float bzz[4] = {bz4.x, bz4.y, bz4.z, bz4.w};
        const float bnn[4] = {bn4.x, bn4.y, bn4.z, bn4.w};

        float hnew[4];
#pragma unroll
        for (int ji = 0; ji < 4; ji++) {
            const float ho = sh[(jb + j_r + ji) * 16 + m_r];
            const float r = sigm(grr[ji] + ghr[ji] + brr[ji]);
            const float z = sigm(gzz[ji] + ghz[ji] + bzz[ji]);
            const float n = tanh_fast(gnn[ji] + r * (ghn[ji] + bnn[ji]));
            hnew[ji] = (1.f - z) * n + z * ho;
        }

        // publish slice via L2 (R5)
        {
            float* dst = wb + (size_t)b_r * HH + jb + j_r;
            asm volatile("st.global.cg.v4.f32 [%0], {%1,%2,%3,%4};"
                         :: "l"(dst), "f"(hnew[0]), "f"(hnew[1]),
                            "f"(hnew[2]), "f"(hnew[3]));
        }

        __syncthreads();   // all stores of this step done
        if (tid == 0) {
            asm volatile("red.release.gpu.global.add.u32 [%0], %1;"
                         :: "l"(flagp), "r"(1) : "memory");
        }

        // off-critical-path outputs
        if (write_seq) {
            float4 hv4;
            hv4.x = hnew[0]; hv4.y = hnew[1]; hv4.z = hnew[2]; hv4.w = hnew[3];
            *(float4*)(hseq + ((size_t)b_r * TT + t) * HH + jb + j_r) = hv4;
        }
        if (t == TT - 1) {
            float4 hv4;
            hv4.x = hnew[0]; hv4.y = hnew[1]; hv4.z = hnew[2]; hv4.w = hnew[3];
            *(float4*)(hfin + (size_t)b_r * HH + jb + j_r) = hv4;
        }
    }
}

// ---------------------------------------------------------------------------
// Final FC
// ---------------------------------------------------------------------------
__global__ __launch_bounds__(128) void fc_kernel(
    const float* __restrict__ hfin, const float* __restrict__ W,
    const float* __restrict__ bias, float* __restrict__ out)
{
    __shared__ float hs[HH];
    const int b = blockIdx.x;
    const float* hrow = hfin + (size_t)b * HH;
    for (int i = threadIdx.x; i < HH; i += 128) hs[i] = hrow[i];
    __syncthreads();
    const int o = threadIdx.x;
    if (o < OUTD) {
        float acc = bias[o];
        const float* wr = W + (size_t)o * HH;
#pragma unroll 8
        for (int k = 0; k < HH; k++) acc += hs[k] * wr[k];
        out[(size_t)b * OUTD + o] = acc;
    }
}

// ---------------------------------------------------------------------------
extern "C" void kernel_launch(void* const* d_in, const int* in_sizes, int n_in,
                              void* d_out, int out_size)
{
    const float* x    = (const float*)d_in[0];
    const float* Wih0 = (const float*)d_in[1];
    const float* Whh0 = (const float*)d_in[2];
    const float* bih0 = (const float*)d_in[3];
    const float* bhh0 = (const float*)d_in[4];
    const float* Wih1 = (const float*)d_in[5];
    const float* Whh1 = (const float*)d_in[6];
    const float* bih1 = (const float*)d_in[7];
    const float* bhh1 = (const float*)d_in[8];
    const float* fcW  = (const float*)d_in[9];
    const float* fcb  = (const float*)d_in[10];
    float* out = (float*)d_out;

    float *gx, *hseq, *hA, *hB, *hfin;
    int* flags;
    cudaGetSymbolAddress((void**)&gx, g_gx);
    cudaGetSymbolAddress((void**)&hseq, g_hseq);
    cudaGetSymbolAddress((void**)&hA, g_hA);
    cudaGetSymbolAddress((void**)&hB, g_hB);
    cudaGetSymbolAddress((void**)&hfin, g_hfin);
    cudaGetSymbolAddress((void**)&flags, g_flags);

    static bool attr_set = false;
    if (!attr_set) {
        cudaFuncSetAttribute(gru_layer_kernel,
                             cudaFuncAttributeMaxDynamicSharedMemorySize,
                             LAYER_SMEM_FLOATS * (int)sizeof(float));
        cudaFuncSetAttribute(gemm_tf32_kernel,
                             cudaFuncAttributeMaxDynamicSharedMemorySize,
                             64 * 1024);
        attr_set = true;
    }

    const dim3 gemmGrid(G3 / 128, (BATCH * TT) / 128);
    const dim3 layerGrid(8, 16);
    const int layerSmem = LAYER_SMEM_FLOATS * (int)sizeof(float);
    const int gemmSmem = 64 * 1024;

    // ---- layer 0 ----
    gemm_tf32_kernel<<<gemmGrid, 256, gemmSmem>>>(x, Wih0, bih0, gx, BATCH * TT, DIN);
    cudaMemsetAsync(hA, 0, BATCH * HH * sizeof(float));
    cudaMemsetAsync(flags, 0, 16 * 32 * sizeof(int));
    gru_layer_kernel<<<layerGrid, 128, layerSmem>>>(
        hA, hB, Whh0, bhh0, gx, hseq, hfin, flags, 1);

    // ---- layer 1 (no hseq; final h -> hfin) ----
    gemm_tf32_kernel<<<gemmGrid, 256, gemmSmem>>>(hseq, Wih1, bih1, gx, BATCH * TT, HH);
    cudaMemsetAsync(hA, 0, BATCH * HH * sizeof(float));
    cudaMemsetAsync(flags, 0, 16 * 32 * sizeof(int));
    gru_layer_kernel<<<layerGrid, 128, layerSmem>>>(
        hA, hB, Whh1, bhh1, gx, hseq, hfin, flags, 0);

    // ---- final FC ----
    fc_kernel<<<BATCH, 128>>>(hfin, fcW, fcb, out);
}

// round 15
// speedup vs baseline: 11.1031x; 1.3349x over previous
#include <cuda_runtime.h>
#include <cuda_bf16.h>
#include <math.h>

// Problem constants
#define BATCH 256
#define TT    200
#define DIN   128
#define HH    256
#define OUTD  118
#define G3    768   // 3*H

typedef unsigned long long ull;
typedef unsigned int uint;

// packed fp32x2 helpers
#define FMA2(acc, a, b) \
    asm("fma.rn.f32x2 %0, %1, %2, %0;" : "+l"(acc) : "l"(a), "l"(b))
#define PACK2(d, f) \
    asm("mov.b64 %0, {%1, %1};" : "=l"(d) : "f"(f))
#define UNPACK2(lo, hi, v) \
    asm("mov.b64 {%0, %1}, %2;" : "=f"(lo), "=f"(hi) : "l"(v))

__device__ __forceinline__ uint f2tf32(float f) {
    uint u;
    asm("cvt.rna.tf32.f32 %0, %1;" : "=r"(u) : "f"(f));
    return u;
}

// ---------------- scratch (static device globals; no allocation) -------------
__device__ float g_gx[(size_t)BATCH * TT * G3];
__device__ float g_hseq[(size_t)BATCH * TT * HH];
__device__ float g_hA[BATCH * HH];
__device__ float g_hB[BATCH * HH];
__device__ float g_hfin[BATCH * HH];
__device__ int   g_flags[16 * 32];   // one flag per group, 128B padded

// ---------------------------------------------------------------------------
// tf32 tensor-core GEMM (unchanged from R4)
// ---------------------------------------------------------------------------
__global__ __launch_bounds__(256) void gemm_tf32_kernel(
    const float* __restrict__ A, const float* __restrict__ W,
    const float* __restrict__ bias, float* __restrict__ C,
    int M, int K)
{
    extern __shared__ uint smemU[];
    const int nb = blockIdx.x * 128;
    const int mb = blockIdx.y * 128;
    const int tid = threadIdx.x;
    const int wid = tid >> 5;
    const int lane = tid & 31;
    const int wm = wid & 1;
    const int wn = wid >> 1;
    const int r = lane >> 2;
    const int c = lane & 3;

    const float* gA = A + (size_t)mb * K;
    const float* gW = W + (size_t)nb * K;

    float acc[4][4][4];
#pragma unroll
    for (int i = 0; i < 4; i++)
#pragma unroll
        for (int j = 0; j < 4; j++)
#pragma unroll
            for (int q = 0; q < 4; q++) acc[i][j][q] = 0.f;

    const int nk = K >> 5;

    float4 pa[4], pb[4];
#pragma unroll
    for (int j = 0; j < 4; j++) {
        const int i = tid + j * 256;
        const int m = i >> 3;
        const int k4 = (i & 7) << 2;
        pa[j] = *(const float4*)(gA + (size_t)m * K + k4);
        pb[j] = *(const float4*)(gW + (size_t)m * K + k4);
    }

    for (int kc = 0; kc < nk; kc++) {
        uint* sA = smemU + (kc & 1) * 8192;
        uint* sB = sA + 4096;

#pragma unroll
        for (int j = 0; j < 4; j++) {
            const int i = tid + j * 256;
            const int m = i >> 3;
            const int k4 = (i & 7) << 2;
            const int base = m * 32 + ((((k4 >> 2) ^ (m & 7)) << 2));
            uint4 ua, ub;
            ua.x = f2tf32(pa[j].x); ua.y = f2tf32(pa[j].y);
            ua.z = f2tf32(pa[j].z); ua.w = f2tf32(pa[j].w);
            ub.x = f2tf32(pb[j].x); ub.y = f2tf32(pb[j].y);
            ub.z = f2tf32(pb[j].z); ub.w = f2tf32(pb[j].w);
            *(uint4*)(sA + base) = ua;
            *(uint4*)(sB + base) = ub;
        }
        __syncthreads();

        if (kc + 1 < nk) {
            const int kb = (kc + 1) << 5;
#pragma unroll
            for (int j = 0; j < 4; j++) {
                const int i = tid + j * 256;
                const int m = i >> 3;
                const int k4 = (i & 7) << 2;
                pa[j] = *(const float4*)(gA + (size_t)m * K + kb + k4);
                pb[j] = *(const float4*)(gW + (size_t)m * K + kb + k4);
            }
        }

#pragma unroll
        for (int kf = 0; kf < 4; kf++) {
            const int k0 = kf * 8 + c;
            const int k1 = k0 + 4;
            uint b0[4], b1[4];
#pragma unroll
            for (int nf = 0; nf < 4; nf++) {
                const int n = wn * 32 + nf * 8 + r;
                b0[nf] = sB[n * 32 + (((k0 >> 2) ^ (n & 7)) << 2) + (k0 & 3)];
                b1[nf] = sB[n * 32 + (((k1 >> 2) ^ (n & 7)) << 2) + (k1 & 3)];
            }
#pragma unroll
            for (int mf = 0; mf < 4; mf++) {
                const int m0 = wm * 64 + mf * 16 + r;
                const int m1 = m0 + 8;
                const uint a0 = sA[m0 * 32 + (((k0 >> 2) ^ (m0 & 7)) << 2) + (k0 & 3)];
                const uint a1 = sA[m1 * 32 + (((k0 >> 2) ^ (m1 & 7)) << 2) + (k0 & 3)];
                const uint a2 = sA[m0 * 32 + (((k1 >> 2) ^ (m0 & 7)) << 2) + (k1 & 3)];
                const uint a3 = sA[m1 * 32 + (((k1 >> 2) ^ (m1 & 7)) << 2) + (k1 & 3)];
#pragma unroll
                for (int nf = 0; nf < 4; nf++) {
                    asm("mma.sync.aligned.m16n8k8.row.col.f32.tf32.tf32.f32 "
                        "{%0,%1,%2,%3}, {%4,%5,%6,%7}, {%8,%9}, {%0,%1,%2,%3};"
                        : "+f"(acc[mf][nf][0]), "+f"(acc[mf][nf][1]),
                          "+f"(acc[mf][nf][2]), "+f"(acc[mf][nf][3])
                        : "r"(a0), "r"(a1), "r"(a2), "r"(a3),
                          "r"(b0[nf]), "r"(b1[nf]));
                }
            }
        }
        __syncthreads();
    }

#pragma unroll
    for (int nf = 0; nf < 4; nf++) {
        const int n = nb + wn * 32 + nf * 8 + c * 2;
        const float bb0 = bias[n], bb1 = bias[n + 1];
#pragma unroll
        for (int mf = 0; mf < 4; mf++) {
            const int m0 = mb + wm * 64 + mf * 16 + r;
            float2 v0, v1;
            v0.x = acc[mf][nf][0] + bb0; v0.y = acc[mf][nf][1] + bb1;
            v1.x = acc[mf][nf][2] + bb0; v1.y = acc[mf][nf][3] + bb1;
            *(float2*)(C + (size_t)m0 * G3 + n)       = v0;
            *(float2*)(C + (size_t)(m0 + 8) * G3 + n) = v1;
        }
    }
}

// ---------------------------------------------------------------------------
// Persistent GRU layer kernel — R13 structure with three micros:
// (1) float4 stage loads, (2) own-chunk kept in smem (no L2 round trip,
//     no t=0 staging, no hA memsets), (3) all-thread poll (one barrier less).
// ---------------------------------------------------------------------------
#define SW_FLOATS (3 * 256 * 32)
#define SH_FLOATS (256 * 16)
#define SP_FLOATS (4 * 3 * 16 * 32)
#define LAYER_SMEM_FLOATS (SW_FLOATS + SH_FLOATS + SP_FLOATS)

__device__ __forceinline__ float sigm(float x) {
    return __fdividef(1.f, 1.f + __expf(-x));
}
__device__ __forceinline__ float tanh_fast(float x) {
    return 1.f - 2.f * __fdividef(1.f, __expf(2.f * x) + 1.f);
}

__global__ __launch_bounds__(128) void gru_layer_kernel(
    float* __restrict__ hA, float* __restrict__ hB,
    const float* __restrict__ Whh, const float* __restrict__ bhh,
    const float* __restrict__ gx,
    float* __restrict__ hseq,
    float* __restrict__ hfin,
    int* __restrict__ flags,
    int write_seq)
{
    extern __shared__ float smem[];
    float* sW = smem;                       // [(g*256+k)*32 + j]
    float* sh = smem + SW_FLOATS;           // [k*16 + m]
    float* sp = sh + SH_FLOATS;             // [((w*3+g)*16+m)*32 + j]

    const int jt = blockIdx.x;
    const int mt = blockIdx.y;
    const int jb = jt * 32;
    const int mb = mt * 16;
    const int tid = threadIdx.x;
    const int wid = tid >> 5;
    const int lane = tid & 31;

    // FMA-loop lane mapping
    const int mq = (lane >> 3) * 4;         // m-quad base
    const int j0 = (lane & 7) * 4;          // j-quad base
    const int k0 = wid * 64;                // K slice

    // reduction mapping: 4 consecutive j per thread
    const int m_r = tid >> 3;               // 0..15
    const int j_r = (tid & 7) * 4;          // 0..28

    // ---- one-time: zero h stage (h(0)=0), load Whh tile ----
    for (int i = tid; i < SH_FLOATS; i += 128) sh[i] = 0.f;
    if (tid < 96) {
        const int g = tid >> 5;
        const int j = tid & 31;
        const float* wrow = Whh + (size_t)(g * HH + jb + j) * HH;
        float* dst = sW + (size_t)g * 256 * 32 + j;
#pragma unroll 4
        for (int k = 0; k < 256; k += 4) {
            float4 v = *(const float4*)(wrow + k);
            dst[(k + 0) * 32] = v.x;
            dst[(k + 1) * 32] = v.y;
            dst[(k + 2) * 32] = v.z;
            dst[(k + 3) * 32] = v.w;
        }
    }

    const float4 br4 = *(const float4*)(bhh + jb + j_r);
    const float4 bz4 = *(const float4*)(bhh + HH + jb + j_r);
    const float4 bn4 = *(const float4*)(bhh + 2 * HH + jb + j_r);

    // h-stage loader mapping
    const int sm_ = tid & 15;
    const int skb = (tid >> 4) * 32;
    const bool stage_mine = ((tid >> 4) != jt);   // skip own chunk

    const int b_r = mb + m_r;
    const float* gxb = gx + (size_t)b_r * TT * G3;
    int* const flagp = flags + mt * 32;     // 128B line per group

    __syncthreads();

    for (int t = 0; t < TT; t++) {
        const float* rb = (t & 1) ? hB : hA;
        float*       wb = (t & 1) ? hA : hB;

        // ---- gx prefetch BEFORE the wait (lands during the spin) ----
        const float* gxp = gxb + (size_t)t * G3;
        const float4 gr4 = __ldg((const float4*)(gxp + jb + j_r));
        const float4 gz4 = __ldg((const float4*)(gxp + HH + jb + j_r));
        const float4 gn4 = __ldg((const float4*)(gxp + 2 * HH + jb + j_r));

        if (t > 0) {
            // all-thread poll (coalesced: one request per warp per round)
            {
                const int tgt = 8 * t;
                int v;
                do {
                    asm volatile("ld.global.acquire.gpu.b32 %0, [%1];"
                                 : "=r"(v) : "l"(flagp));
                } while (v < tgt);
            }
            // stage h tile [k][16m], float4 loads, own chunk skipped
            if (stage_mine) {
                const float* src = rb + (size_t)(mb + sm_) * HH + skb;
#pragma unroll
                for (int i = 0; i < 32; i += 4) {
                    const float4 v = __ldcg((const float4*)(src + i));
                    sh[(skb + i + 0) * 16 + sm_] = v.x;
                    sh[(skb + i + 1) * 16 + sm_] = v.y;
                    sh[(skb + i + 2) * 16 + sm_] = v.z;
                    sh[(skb + i + 3) * 16 + sm_] = v.w;
                }
            }
        }
        __syncthreads();

        // ---- warp-split-K FMA loop ----
        ull acc[4][3][2];
#pragma unroll
        for (int m = 0; m < 4; m++)
#pragma unroll
            for (int g = 0; g < 3; g++) {
                acc[m][g][0] = 0ull;
                acc[m][g][1] = 0ull;
            }
        {
            const float* hP  = sh + k0 * 16 + mq;
            const float* w0P = sW + (size_t)(0 * 256 + k0) * 32 + j0;
            const float* w1P = sW + (size_t)(1 * 256 + k0) * 32 + j0;
            const float* w2P = sW + (size_t)(2 * 256 + k0) * 32 + j0;
#pragma unroll 4
            for (int kk = 0; kk < 64; kk++) {
                const float4 hq = *(const float4*)(hP + kk * 16);
                ull h0, h1, h2, h3;
                PACK2(h0, hq.x); PACK2(h1, hq.y);
                PACK2(h2, hq.z); PACK2(h3, hq.w);

                const ull* wr = (const ull*)(w0P + (size_t)kk * 32);
                const ull wr0 = wr[0], wr1 = wr[1];
                FMA2(acc[0][0][0], h0, wr0); FMA2(acc[0][0][1], h0, wr1);
                FMA2(acc[1][0][0], h1, wr0); FMA2(acc[1][0][1], h1, wr1);
                FMA2(acc[2][0][0], h2, wr0); FMA2(acc[2][0][1], h2, wr1);
                FMA2(acc[3][0][0], h3, wr0); FMA2(acc[3][0][1], h3, wr1);

                const ull* wz = (const ull*)(w1P + (size_t)kk * 32);
                const ull wz0 = wz[0], wz1 = wz[1];
                FMA2(acc[0][1][0], h0, wz0); FMA2(acc[0][1][1], h0, wz1);
                FMA2(acc[1][1][0], h1, wz0); FMA2(acc[1][1][1], h1, wz1);
                FMA2(acc[2][1][0], h2, wz0); FMA2(acc[2][1][1], h2, wz1);
                FMA2(acc[3][1][0], h3, wz0); FMA2(acc[3][1][1], h3, wz1);

                const ull* wn = (const ull*)(w2P + (size_t)kk * 32);
                const ull wn0 = wn[0], wn1 = wn[1];
                FMA2(acc[0][2][0], h0, wn0); FMA2(acc[0][2][1], h0, wn1);
                FMA2(acc[1][2][0], h1, wn0); FMA2(acc[1][2][1], h1, wn1);
                FMA2(acc[2][2][0], h2, wn0); FMA2(acc[2][2][1], h2, wn1);
                FMA2(acc[3][2][0], h3, wn0); FMA2(acc[3][2][1], h3, wn1);
            }
        }

        // store partials
#pragma unroll
        for (int m = 0; m < 4; m++) {
#pragma unroll
            for (int g = 0; g < 3; g++) {
                ull* dst = (ull*)(sp + (size_t)(((wid * 3 + g) * 16) + mq + m) * 32 + j0);
                dst[0] = acc[m][g][0];
                dst[1] = acc[m][g][1];
            }
        }
        __syncthreads();   // (A) partials ready; all sh reads done

        // ---- reduce across 4 warps + gates ----
        float ghr[4], ghz[4], ghn[4];
        {
            float4 s0, s1, s2, s3;
            s0 = *(const float4*)(sp + (size_t)((0 * 3 + 0) * 16 + m_r) * 32 + j_r);
            s1 = *(const float4*)(sp + (size_t)((1 * 3 + 0) * 16 + m_r) * 32 + j_r);
            s2 = *(const float4*)(sp + (size_t)((2 * 3 + 0) * 16 + m_r) * 32 + j_r);
            s3 = *(const float4*)(sp + (size_t)((3 * 3 + 0) * 16 + m_r) * 32 + j_r);
            ghr[0] = (s0.x + s1.x) + (s2.x + s3.x);
            ghr[1] = (s0.y + s1.y) + (s2.y + s3.y);
            ghr[2] = (s0.z + s1.z) + (s2.z + s3.z);
            ghr[3] = (s0.w + s1.w) + (s2.w + s3.w);
            s0 = *(const float4*)(sp + (size_t)((0 * 3 + 1) * 16 + m_r) * 32 + j_r);
            s1 = *(const float4*)(sp + (size_t)((1 * 3 + 1) * 16 + m_r) * 32 + j_r);
            s2 = *(const float4*)(sp + (size_t)((2 * 3 + 1) * 16 + m_r) * 32 + j_r);
            s3 = *(const float4*)(sp + (size_t)((3 * 3 + 1) * 16 + m_r) * 32 + j_r);
            ghz[0] = (s0.x + s1.x) + (s2.x + s3.x);
            ghz[1] = (s0.y + s1.y) + (s2.y + s3.y);
            ghz[2] = (s0.z + s1.z) + (s2.z + s3.z);
            ghz[3] = (s0.w + s1.w) + (s2.w + s3.w);
            s0 = *(const float4*)(sp + (size_t)((0 * 3 + 2) * 16 + m_r) * 32 + j_r);
            s1 = *(const float4*)(sp + (size_t)((1 * 3 + 2) * 16 + m_r) * 32 + j_r);
            s2 = *(const float4*)(sp + (size_t)((2 * 3 + 2) * 16 + m_r) * 32 + j_r);
            s3 = *(const float4*)(sp + (size_t)((3 * 3 + 2) * 16 + m_r) * 32 + j_r);
            ghn[0] = (s0.x + s1.x) + (s2.x + s3.x);
            ghn[1] = (s0.y + s1.y) + (s2.y + s3.y);
            ghn[2] = (s0.z + s1.z) + (s2.z + s3.z);
            ghn[3] = (s0.w + s1.w) + (s2.w + s3.w);
        }

        const float grr[4] = {gr4.x, gr4.y, gr4.z, gr4.w};
        const float gzz[4] = {gz4.x, gz4.y, gz4.z, gz4.w};
        const float gnn[4] = {gn4.x, gn4.y, gn4.z, gn4.w};
        const float brr[4] = {br4.x, br4.y, br4.z, br4.w};
        const float bzz[4] = {bz4.x, bz4.y, bz4.z, bz4.w};
        const float bnn[4] = {bn4.x, bn4.y, bn4.z, bn4.w};

        float hnew[4];
#pragma unroll
        for (int ji = 0; ji < 4; ji++) {
            const float ho = sh[(jb + j_r + ji) * 16 + m_r];
            const float r = sigm(grr[ji] + ghr[ji] + brr[ji]);
            const float z = sigm(gzz[ji] + ghz[ji] + bzz[ji]);
            const float n = tanh_fast(gnn[ji] + r * (ghn[ji] + bnn[ji]));
            hnew[ji] = (1.f - z) * n + z * ho;
        }

        // own chunk straight into sh for next step (same slot, same thread)
#pragma unroll
        for (int ji = 0; ji < 4; ji++)
            sh[(jb + j_r + ji) * 16 + m_r] = hnew[ji];

        // publish slice via L2 for peer CTAs
        {
            float* dst = wb + (size_t)b_r * HH + jb + j_r;
            asm volatile("st.global.cg.v4.f32 [%0], {%1,%2,%3,%4};"
                         :: "l"(dst), "f"(hnew[0]), "f"(hnew[1]),
                            "f"(hnew[2]), "f"(hnew[3]));
        }

        __syncthreads();   // (B) all stores + sh own-chunk writes done
        if (tid == 0) {
            asm volatile("red.release.gpu.global.add.u32 [%0], %1;"
                         :: "l"(flagp), "r"(1) : "memory");
        }

        // off-critical-path outputs
        if (write_seq) {
            float4 hv4;
            hv4.x = hnew[0]; hv4.y = hnew[1]; hv4.z = hnew[2]; hv4.w = hnew[3];
            *(float4*)(hseq + ((size_t)b_r * TT + t) * HH + jb + j_r) = hv4;
        }
        if (t == TT - 1) {
            float4 hv4;
            hv4.x = hnew[0]; hv4.y = hnew[1]; hv4.z = hnew[2]; hv4.w = hnew[3];
            *(float4*)(hfin + (size_t)b_r * HH + jb + j_r) = hv4;
        }
    }
}

// ---------------------------------------------------------------------------
// Final FC
// ---------------------------------------------------------------------------
__global__ __launch_bounds__(128) void fc_kernel(
    const float* __restrict__ hfin, const float* __restrict__ W,
    const float* __restrict__ bias, float* __restrict__ out)
{
    __shared__ float hs[HH];
    const int b = blockIdx.x;
    const float* hrow = hfin + (size_t)b * HH;
    for (int i = threadIdx.x; i < HH; i += 128) hs[i] = hrow[i];
    __syncthreads();
    const int o = threadIdx.x;
    if (o < OUTD) {
        float acc = bias[o];
        const float* wr = W + (size_t)o * HH;
#pragma unroll 8
        for (int k = 0; k < HH; k++) acc += hs[k] * wr[k];
        out[(size_t)b * OUTD + o] = acc;
    }
}

// ---------------------------------------------------------------------------
extern "C" void kernel_launch(void* const* d_in, const int* in_sizes, int n_in,
                              void* d_out, int out_size)
{
    const float* x    = (const float*)d_in[0];
    const float* Wih0 = (const float*)d_in[1];
    const float* Whh0 = (const float*)d_in[2];
    const float* bih0 = (const float*)d_in[3];
    const float* bhh0 = (const float*)d_in[4];
    const float* Wih1 = (const float*)d_in[5];
    const float* Whh1 = (const float*)d_in[6];
    const float* bih1 = (const float*)d_in[7];
    const float* bhh1 = (const float*)d_in[8];
    const float* fcW  = (const float*)d_in[9];
    const float* fcb  = (const float*)d_in[10];
    float* out = (float*)d_out;

    float *gx, *hseq, *hA, *hB, *hfin;
    int* flags;
    cudaGetSymbolAddress((void**)&gx, g_gx);
    cudaGetSymbolAddress((void**)&hseq, g_hseq);
    cudaGetSymbolAddress((void**)&hA, g_hA);
    cudaGetSymbolAddress((void**)&hB, g_hB);
    cudaGetSymbolAddress((void**)&hfin, g_hfin);
    cudaGetSymbolAddress((void**)&flags, g_flags);

    static bool attr_set = false;
    if (!attr_set) {
        cudaFuncSetAttribute(gru_layer_kernel,
                             cudaFuncAttributeMaxDynamicSharedMemorySize,
                             LAYER_SMEM_FLOATS * (int)sizeof(float));
        cudaFuncSetAttribute(gemm_tf32_kernel,
                             cudaFuncAttributeMaxDynamicSharedMemorySize,
                             64 * 1024);
        attr_set = true;
    }

    const dim3 gemmGrid(G3 / 128, (BATCH * TT) / 128);
    const dim3 layerGrid(8, 16);
    const int layerSmem = LAYER_SMEM_FLOATS * (int)sizeof(float);
    const int gemmSmem = 64 * 1024;

    // ---- layer 0 ----
    gemm_tf32_kernel<<<gemmGrid, 256, gemmSmem>>>(x, Wih0, bih0, gx, BATCH * TT, DIN);
    cudaMemsetAsync(flags, 0, 16 * 32 * sizeof(int));
    gru_layer_kernel<<<layerGrid, 128, layerSmem>>>(
        hA, hB, Whh0, bhh0, gx, hseq, hfin, flags, 1);

    // ---- layer 1 (no hseq; final h -> hfin) ----
    gemm_tf32_kernel<<<gemmGrid, 256, gemmSmem>>>(hseq, Wih1, bih1, gx, BATCH * TT, HH);
    cudaMemsetAsync(flags, 0, 16 * 32 * sizeof(int));
    gru_layer_kernel<<<layerGrid, 128, layerSmem>>>(
        hA, hB, Whh1, bhh1, gx, hseq, hfin, flags, 0);

    // ---- final FC ----
    fc_kernel<<<BATCH, 128>>>(hfin, fcW, fcb, out);
}